// round 3
// baseline (speedup 1.0000x reference)
#include <cuda_runtime.h>
#include <cstdint>

// ---------------------------------------------------------------------------
// TreeLSTMCell fused kernel (fp32 / FFMA2 baseline).
//
// Inputs (metadata order):
//  0 x[N,128] f32, 1 h[N,128] f32, 2 c[N,128] f32, 3 children[N,2] i32,
//  4 is_leaf[N,1] i32, 5 W_iou[384,128], 6 b_Wiou[384], 7 U_iou[384,256],
//  8 b_Uiou[384], 9 U_f[256,256], 10 b_Uf[256]
// Output: h_new [N,128] then c_new [N,128]  (2*N*128 f32)
//
// Strategy: per-CTA tile of 128 nodes. Gather h_cat (and x-or-zero) into
// smem transposed (k-major). Leaf/internal select is folded into the GEMM by
// zeroing the unused half of each node's combined [h_cat | x] row and using
// the concatenated weight [U_iou | W_iou] (built by a prep kernel into
// __device__ scratch, transposed k-major for conflict-free smem staging).
// GEMM inner loop uses packed fma.rn.f32x2 (2 MACs/instr) — ptxas never
// emits FFMA2 from C++, only from this PTX form.
// ---------------------------------------------------------------------------

#define MT   128   // nodes per block
#define PAD  132   // padded inner stride (floats), 132*4 % 16 == 0, %32 == 4
#define KT   32    // k chunk for weight tile
#define HH   128
#define K2   256
#define KIOU 384

// Pre-transposed weights (k-major), built once per launch by prep_kernel.
__device__ float g_UfT[256 * 256];    // g_UfT[k*256 + o] = U_f[o][k]
__device__ float g_IouT[384 * 384];   // [U_iou | W_iou] combined, k-major

__global__ void prep_kernel(const float* __restrict__ Uf,
                            const float* __restrict__ Uiou,
                            const float* __restrict__ Wiou) {
    int idx = blockIdx.x * blockDim.x + threadIdx.x;
    if (idx < 256 * 256) {
        int k = idx >> 8, o = idx & 255;
        g_UfT[idx] = Uf[o * 256 + k];
    }
    int j = idx - 256 * 256;
    if (j >= 0 && j < 384 * 384) {
        int k = j / 384, o = j - k * 384;
        g_IouT[j] = (k < 256) ? Uiou[o * 256 + k] : Wiou[o * 128 + (k - 256)];
    }
}

__device__ __forceinline__ unsigned long long f2pack(float v) {
    unsigned long long r;
    asm("mov.b64 %0, {%1, %1};" : "=l"(r) : "f"(v));
    return r;
}
__device__ __forceinline__ void ffma2(unsigned long long& a,
                                      unsigned long long x,
                                      unsigned long long y) {
    asm("fma.rn.f32x2 %0, %1, %2, %0;" : "+l"(a) : "l"(x), "l"(y));
}
__device__ __forceinline__ float2 f2unpack(unsigned long long v) {
    float2 r;
    asm("mov.b64 {%0, %1}, %2;" : "=f"(r.x), "=f"(r.y) : "l"(v));
    return r;
}
__device__ __forceinline__ float sigm(float v) {
    return 1.0f / (1.0f + __expf(-v));
}

// C-tile [128 nodes x 128 outs] GEMM: acc += A^T(sAT, k-major) * W^T chunk.
// Thread (ty,tx): rows ty*8..+7, cols tx*8..+7. acc[i*4+jp] = cols (2jp,2jp+1).
__device__ __forceinline__ void gemm128(const float* __restrict__ gT, int OD,
                                        int outBase, int K,
                                        const float* sAT, float* sW,
                                        unsigned long long acc[32],
                                        int ty, int tx, int tid) {
#pragma unroll
    for (int i = 0; i < 32; i++) acc[i] = 0ULL;
    for (int k0 = 0; k0 < K; k0 += KT) {
        __syncthreads();  // previous chunk consumers done
#pragma unroll
        for (int r = 0; r < (KT * 128) / 256; r++) {
            int idx = tid + r * 256;
            int kk = idx >> 7, o = idx & 127;
            sW[kk * PAD + o] = gT[(k0 + kk) * OD + outBase + o];
        }
        __syncthreads();
#pragma unroll 4
        for (int kk = 0; kk < KT; kk++) {
            const float* arow = sAT + (k0 + kk) * PAD + ty * 8;
            float4 a0 = *(const float4*)(arow);
            float4 a1 = *(const float4*)(arow + 4);
            const ulonglong2* bp = (const ulonglong2*)(sW + kk * PAD + tx * 8);
            ulonglong2 b0 = bp[0];
            ulonglong2 b1 = bp[1];
            unsigned long long ap[8];
            ap[0] = f2pack(a0.x); ap[1] = f2pack(a0.y);
            ap[2] = f2pack(a0.z); ap[3] = f2pack(a0.w);
            ap[4] = f2pack(a1.x); ap[5] = f2pack(a1.y);
            ap[6] = f2pack(a1.z); ap[7] = f2pack(a1.w);
#pragma unroll
            for (int i = 0; i < 8; i++) {
                ffma2(acc[i * 4 + 0], ap[i], b0.x);
                ffma2(acc[i * 4 + 1], ap[i], b0.y);
                ffma2(acc[i * 4 + 2], ap[i], b1.x);
                ffma2(acc[i * 4 + 3], ap[i], b1.y);
            }
        }
    }
}

__global__ void __launch_bounds__(256, 1)
tree_kernel(const float* __restrict__ x, const float* __restrict__ h,
            const float* __restrict__ c, const int* __restrict__ children,
            const int* __restrict__ is_leaf,
            const float* __restrict__ bWiou, const float* __restrict__ bUiou,
            const float* __restrict__ bUf,
            float* __restrict__ out, int N) {
    extern __shared__ float sm[];
    float* sAT  = sm;                    // [384][132] combined A, k-major
    float* sW   = sAT + KIOU * PAD;      // [32][132] weight chunk
    float* sbUf = sW + KT * PAD;         // 256
    float* sbI  = sbUf + 256;            // 384
    float* sbW  = sbI + 384;             // 384
    int*   sCh  = (int*)(sbW + 384);     // 256
    int*   sLf  = sCh + 256;             // 128

    const int tid = threadIdx.x;
    const int ty = tid >> 4, tx = tid & 15;
    const int base = blockIdx.x * MT;
    const int row0 = ty * 8;

    // biases + per-node metadata into smem
    sbUf[tid] = bUf[tid];
    sbI[tid] = bUiou[tid];
    sbW[tid] = bWiou[tid];
    if (tid < 128) {
        sbI[256 + tid] = bUiou[256 + tid];
        sbW[256 + tid] = bWiou[256 + tid];
        sLf[tid] = is_leaf[base + tid];
    }
    sCh[tid] = children[base * 2 + tid];
    __syncthreads();

    // Gather combined A rows, stored transposed (k-major):
    //  k <128  : h[child0][k]            (all nodes; needed for f)
    //  k 128..255: h[child1][k-128]
    //  k 256..383: leaf ? x[node][k-256] : 0
    for (int idx = tid; idx < MT * KIOU; idx += 256) {
        int m = idx / KIOU;
        int k = idx - m * KIOU;
        float v;
        if (k < 128)      v = h[(size_t)sCh[2 * m] * HH + k];
        else if (k < 256) v = h[(size_t)sCh[2 * m + 1] * HH + (k - 128)];
        else              v = sLf[m] ? x[(size_t)(base + m) * HH + (k - 256)] : 0.0f;
        sAT[k * PAD + m] = v;
    }
    // (gemm128's first __syncthreads orders this before any A reads)

    unsigned long long acc[32];
    float cf[64];   // c_f fragment, later reused for tanh(c_new)
    float si[64];   // sigmoid(i) fragment

    // ---- f gate, child 0 half (U_f rows 0..127) ----
    gemm128(g_UfT, 256, 0, K2, sAT, sW, acc, ty, tx, tid);
#pragma unroll
    for (int i = 0; i < 8; i++) {
        int ch0 = sCh[2 * (row0 + i)];
        const float4* cp = (const float4*)(c + (size_t)ch0 * HH + tx * 8);
        float4 c0 = __ldg(cp), c1 = __ldg(cp + 1);
        float cv[8] = {c0.x, c0.y, c0.z, c0.w, c1.x, c1.y, c1.z, c1.w};
#pragma unroll
        for (int jp = 0; jp < 4; jp++) {
            float2 v = f2unpack(acc[i * 4 + jp]);
            int g = tx * 8 + jp * 2;
            cf[i * 8 + jp * 2]     = sigm(v.x + sbUf[g])     * cv[jp * 2];
            cf[i * 8 + jp * 2 + 1] = sigm(v.y + sbUf[g + 1]) * cv[jp * 2 + 1];
        }
    }

    // ---- f gate, child 1 half (U_f rows 128..255) ----
    gemm128(g_UfT, 256, 128, K2, sAT, sW, acc, ty, tx, tid);
#pragma unroll
    for (int i = 0; i < 8; i++) {
        int ch1 = sCh[2 * (row0 + i) + 1];
        const float4* cp = (const float4*)(c + (size_t)ch1 * HH + tx * 8);
        float4 c0 = __ldg(cp), c1 = __ldg(cp + 1);
        float cv[8] = {c0.x, c0.y, c0.z, c0.w, c1.x, c1.y, c1.z, c1.w};
#pragma unroll
        for (int jp = 0; jp < 4; jp++) {
            float2 v = f2unpack(acc[i * 4 + jp]);
            int g = tx * 8 + jp * 2;
            cf[i * 8 + jp * 2]     += sigm(v.x + sbUf[128 + g])     * cv[jp * 2];
            cf[i * 8 + jp * 2 + 1] += sigm(v.y + sbUf[128 + g + 1]) * cv[jp * 2 + 1];
        }
    }

    // ---- zero h_cat part of leaf rows so the combined iou GEMM selects ----
    __syncthreads();  // all f-GEMM reads of sAT complete
    for (int idx = tid; idx < MT * K2; idx += 256) {
        int m = idx >> 8;
        int k = idx & 255;
        if (sLf[m]) sAT[k * PAD + m] = 0.0f;
    }
    // (next gemm128's first __syncthreads orders these writes)

    // ---- i gate (combined outs 0..127, K=384) ----
    gemm128(g_IouT, 384, 0, KIOU, sAT, sW, acc, ty, tx, tid);
#pragma unroll
    for (int i = 0; i < 8; i++) {
        const float* bb = sLf[row0 + i] ? sbW : sbI;
#pragma unroll
        for (int jp = 0; jp < 4; jp++) {
            float2 v = f2unpack(acc[i * 4 + jp]);
            int g = tx * 8 + jp * 2;
            si[i * 8 + jp * 2]     = sigm(v.x + bb[g]);
            si[i * 8 + jp * 2 + 1] = sigm(v.y + bb[g + 1]);
        }
    }

    // ---- u gate (outs 256..383): c_new = sig(i)*tanh(u) + c_f ----
    gemm128(g_IouT, 384, 256, KIOU, sAT, sW, acc, ty, tx, tid);
    float* outc = out + (size_t)N * HH;
#pragma unroll
    for (int i = 0; i < 8; i++) {
        const float* bb = sLf[row0 + i] ? sbW : sbI;
        float t0[8];
#pragma unroll
        for (int jp = 0; jp < 4; jp++) {
            float2 v = f2unpack(acc[i * 4 + jp]);
            int g = tx * 8 + jp * 2;
            float cn0 = si[i * 8 + jp * 2]     * tanhf(v.x + bb[256 + g])     + cf[i * 8 + jp * 2];
            float cn1 = si[i * 8 + jp * 2 + 1] * tanhf(v.y + bb[256 + g + 1]) + cf[i * 8 + jp * 2 + 1];
            t0[jp * 2] = cn0; t0[jp * 2 + 1] = cn1;
            cf[i * 8 + jp * 2]     = tanhf(cn0);   // reuse cf for tanh(c_new)
            cf[i * 8 + jp * 2 + 1] = tanhf(cn1);
        }
        float* oc = outc + (size_t)(base + row0 + i) * HH + tx * 8;
        *(float4*)(oc)     = make_float4(t0[0], t0[1], t0[2], t0[3]);
        *(float4*)(oc + 4) = make_float4(t0[4], t0[5], t0[6], t0[7]);
    }

    // ---- o gate (outs 128..255): h_new = sig(o)*tanh(c_new) ----
    gemm128(g_IouT, 384, 128, KIOU, sAT, sW, acc, ty, tx, tid);
#pragma unroll
    for (int i = 0; i < 8; i++) {
        const float* bb = sLf[row0 + i] ? sbW : sbI;
        float t0[8];
#pragma unroll
        for (int jp = 0; jp < 4; jp++) {
            float2 v = f2unpack(acc[i * 4 + jp]);
            int g = tx * 8 + jp * 2;
            t0[jp * 2]     = sigm(v.x + bb[128 + g])     * cf[i * 8 + jp * 2];
            t0[jp * 2 + 1] = sigm(v.y + bb[128 + g + 1]) * cf[i * 8 + jp * 2 + 1];
        }
        float* oh = out + (size_t)(base + row0 + i) * HH + tx * 8;
        *(float4*)(oh)     = make_float4(t0[0], t0[1], t0[2], t0[3]);
        *(float4*)(oh + 4) = make_float4(t0[4], t0[5], t0[6], t0[7]);
    }
}

static const int SMEM_BYTES =
    (KIOU * PAD + KT * PAD + 256 + 384 + 384) * 4 + (256 + 128) * 4;

extern "C" void kernel_launch(void* const* d_in, const int* in_sizes, int n_in,
                              void* d_out, int out_size) {
    const float* x       = (const float*)d_in[0];
    const float* h       = (const float*)d_in[1];
    const float* c       = (const float*)d_in[2];
    const int*   children= (const int*)d_in[3];
    const int*   is_leaf = (const int*)d_in[4];
    // d_in[5] = W_iou, d_in[6] = b_Wiou, d_in[7] = U_iou, d_in[8] = b_Uiou,
    // d_in[9] = U_f,  d_in[10] = b_Uf
    const float* W_iou  = (const float*)d_in[5];
    const float* b_Wiou = (const float*)d_in[6];
    const float* U_iou  = (const float*)d_in[7];
    const float* b_Uiou = (const float*)d_in[8];
    const float* U_f    = (const float*)d_in[9];
    const float* b_Uf   = (const float*)d_in[10];

    int N = in_sizes[1] / HH;  // h is [N,128]; N = 400000 (multiple of 128)

    cudaFuncSetAttribute(tree_kernel,
                         cudaFuncAttributeMaxDynamicSharedMemorySize,
                         SMEM_BYTES);

    prep_kernel<<<(256 * 256 + 384 * 384 + 255) / 256, 256>>>(U_f, U_iou, W_iou);
    tree_kernel<<<N / MT, 256, SMEM_BYTES>>>(x, h, c, children, is_leaf,
                                             b_Wiou, b_Uiou, b_Uf,
                                             (float*)d_out, N);
}

// round 10
// speedup vs baseline: 3.1977x; 3.1977x over previous
#include <cuda_runtime.h>
#include <cstdint>

// ===========================================================================
// TreeLSTMCell via legacy tensor-core path (mma.sync.m16n8k8.tf32).
// Toolchain targets plain sm_103 -> no tcgen05/TMA-a features; mma.sync,
// cp.async and cvt.rna.tf32 are family-generic and compile.
//
// CTA = 128 nodes, 256 threads, warp grid 2(M)x4(N), warp tile 64x32.
// Five GEMM passes over N-windows of 128:
//   P0: f(child0) = h_cat @ Uf[:,0:128]    K=256  -> out_c = sig(f0)*c_ch0
//   P1: f(child1) = h_cat @ Uf[:,128:256]  K=256  -> out_c += sig(f1)*c_ch1
//   P2: u = maskedA @ Wcomb[:,256:384]     K=384  -> out_h = tanh(u+b)
//   P3: i = maskedA @ Wcomb[:,0:128]       K=384  -> out_c = sig(i+b)*out_h + out_c
//   P4: o = maskedA @ Wcomb[:,128:256]     K=384  -> out_h = sig(o+b)*tanh(out_c)
// maskedA row = leaf ? [0,0,x] : [h_ch0,h_ch1,0]; Wcomb = [U_iou | W_iou]
// (pre-rounded to tf32 by prep kernel into __device__ scratch).
// Inter-pass scalars ride in d_out; each lane re-reads its own addresses.
// ===========================================================================

#define HH   128
#define KC   32          // K per smem chunk
#define PADK 36          // padded row stride (floats); 36%32==4 -> LDS conflict-free
#define SLOT 18432       // 128*36*4 bytes per chunk buffer
#define A0_OFF   0
#define B0_OFF   (2*SLOT)
#define META_OFF (4*SLOT)
#define SMEM_BYTES (META_OFF + 5632)

__device__ float g_Wf[256 * 256];     // Uf, tf32-rounded, row-major [o][k]
__device__ float g_Wiou[384 * 384];   // [U_iou | W_iou] combined, tf32-rounded

__device__ __forceinline__ uint32_t cvt_tf32(float f) {
    uint32_t r;
    asm("cvt.rna.tf32.f32 %0, %1;" : "=r"(r) : "f"(f));
    return r;
}

__global__ void prep_kernel(const float* __restrict__ Uf,
                            const float* __restrict__ Uiou,
                            const float* __restrict__ Wiou) {
    int i = blockIdx.x * blockDim.x + threadIdx.x;
    if (i < 256 * 256) g_Wf[i] = __uint_as_float(cvt_tf32(Uf[i]));
    int j = i - 256 * 256;
    if (j >= 0 && j < 384 * 384) {
        int o = j / 384, k = j - o * 384;
        float v = (k < 256) ? Uiou[o * 256 + k] : Wiou[o * 128 + (k - 256)];
        g_Wiou[j] = __uint_as_float(cvt_tf32(v));
    }
}

__device__ __forceinline__ uint32_t smem_u32(const void* p) {
    uint32_t a;
    asm("{ .reg .u64 t; cvta.to.shared.u64 t, %1; cvt.u32.u64 %0, t; }"
        : "=r"(a) : "l"(p));
    return a;
}
__device__ __forceinline__ void cpa16(uint32_t dst, const void* src, int sz) {
    asm volatile("cp.async.ca.shared.global [%0], [%1], 16, %2;"
                 :: "r"(dst), "l"(src), "r"(sz) : "memory");
}
#define CP_COMMIT() asm volatile("cp.async.commit_group;" ::: "memory")
#define CP_WAIT0()  asm volatile("cp.async.wait_group 0;" ::: "memory")

__device__ __forceinline__ void mma8(float d[4], const uint32_t a[4],
                                     const uint32_t b[2]) {
    asm volatile(
        "mma.sync.aligned.m16n8k8.row.col.f32.tf32.tf32.f32 "
        "{%0,%1,%2,%3}, {%4,%5,%6,%7}, {%8,%9}, {%0,%1,%2,%3};"
        : "+f"(d[0]), "+f"(d[1]), "+f"(d[2]), "+f"(d[3])
        : "r"(a[0]), "r"(a[1]), "r"(a[2]), "r"(a[3]), "r"(b[0]), "r"(b[1]));
}
__device__ __forceinline__ float sigm(float v) { return 1.0f / (1.0f + __expf(-v)); }

// ---- chunk loaders (cp.async, 4 x 16B per thread each) ----
// TYPE 0: unmasked h_cat (F passes).  TYPE 1: masked [h_cat | x] (IOU passes).
template <int TYPE>
__device__ __forceinline__ void loadA(char* dst, int kc,
                                      const float* __restrict__ h,
                                      const float* __restrict__ x,
                                      const int* sCh, const int* sLf,
                                      int base, int tid) {
#pragma unroll
    for (int r = 0; r < 4; r++) {
        int idx = tid + r * 256;
        int m = idx >> 3, s = idx & 7;
        int k = kc * KC + s * 4;
        uint32_t d = smem_u32(dst + (m * PADK + s * 4) * 4);
        const float* src;
        int sz = 16;
        if (TYPE == 0) {
            src = h + (size_t)sCh[2 * m + (k >> 7)] * HH + (k & 127);
        } else {
            int leaf = sLf[m];
            if (k < 256) {
                src = h + (size_t)sCh[2 * m + (k >> 7)] * HH + (k & 127);
                sz = leaf ? 0 : 16;     // zfill leaf rows
            } else {
                src = x + (size_t)(base + m) * HH + (k & 127);
                sz = leaf ? 16 : 0;     // zfill internal rows
            }
        }
        cpa16(d, src, sz);
    }
}

__device__ __forceinline__ void loadB(const float* __restrict__ W, int ldw,
                                      int nb, char* dst, int kc, int tid) {
#pragma unroll
    for (int r = 0; r < 4; r++) {
        int idx = tid + r * 256;
        int n = idx >> 3, s = idx & 7;
        cpa16(smem_u32(dst + (n * PADK + s * 4) * 4),
              W + (size_t)(nb + n) * ldw + kc * KC + s * 4, 16);
    }
}

// ---- one K=32 chunk of warp-tile mma (64 HMMA / warp) ----
__device__ __forceinline__ void compute_chunk(const float* sA, const float* sB,
                                              float acc[4][4][4],
                                              int wm, int wn, int g, int t) {
#pragma unroll
    for (int kk = 0; kk < 4; kk++) {
        uint32_t af[4][4];
#pragma unroll
        for (int mt = 0; mt < 4; mt++) {
            const float* ap = sA + (wm * 64 + mt * 16 + g) * PADK + kk * 8 + t;
            af[mt][0] = cvt_tf32(ap[0]);
            af[mt][1] = cvt_tf32(ap[8 * PADK]);
            af[mt][2] = cvt_tf32(ap[4]);
            af[mt][3] = cvt_tf32(ap[8 * PADK + 4]);
        }
        uint32_t bf[4][2];
#pragma unroll
        for (int nt = 0; nt < 4; nt++) {
            const float* bp = sB + (wn * 32 + nt * 8 + g) * PADK + kk * 8 + t;
            bf[nt][0] = __float_as_uint(bp[0]);
            bf[nt][1] = __float_as_uint(bp[4]);
        }
#pragma unroll
        for (int mt = 0; mt < 4; mt++)
#pragma unroll
            for (int nt = 0; nt < 4; nt++)
                mma8(acc[mt][nt], af[mt], bf[nt]);
    }
}

// ---- per-pass epilogue; lane owns (row,col) = same mapping every pass ----
template <int PASS>
__device__ __forceinline__ void epilogue(float acc[4][4][4],
                                         const float* __restrict__ c,
                                         const int* sCh, const int* sLf,
                                         const float* sbUf, const float* sbI,
                                         const float* sbW,
                                         float* __restrict__ outH,
                                         float* __restrict__ outC,
                                         int base, int wm, int wn, int g, int t) {
#pragma unroll
    for (int mt = 0; mt < 4; mt++) {
#pragma unroll
        for (int hr = 0; hr < 2; hr++) {
            int row = wm * 64 + mt * 16 + hr * 8 + g;
            size_t node = (size_t)(base + row);
            const float* bb = sLf[row] ? sbW : sbI;
            const float* crow = c;  // only used in P0/P1
            if (PASS == 0) crow = c + (size_t)sCh[2 * row] * HH;
            if (PASS == 1) crow = c + (size_t)sCh[2 * row + 1] * HH;
#pragma unroll
            for (int nt = 0; nt < 4; nt++) {
                int col = wn * 32 + nt * 8 + 2 * t;
                float v0 = acc[mt][nt][hr * 2 + 0];
                float v1 = acc[mt][nt][hr * 2 + 1];
                if (PASS == 0) {
                    float2 cc = *(const float2*)(crow + col);
                    float2 r = make_float2(sigm(v0 + sbUf[col]) * cc.x,
                                           sigm(v1 + sbUf[col + 1]) * cc.y);
                    *(float2*)(outC + node * HH + col) = r;
                } else if (PASS == 1) {
                    float2 cc = *(const float2*)(crow + col);
                    float2 old = *(const float2*)(outC + node * HH + col);
                    float2 r = make_float2(
                        old.x + sigm(v0 + sbUf[128 + col]) * cc.x,
                        old.y + sigm(v1 + sbUf[128 + col + 1]) * cc.y);
                    *(float2*)(outC + node * HH + col) = r;
                } else if (PASS == 2) {
                    float2 r = make_float2(tanhf(v0 + bb[256 + col]),
                                           tanhf(v1 + bb[256 + col + 1]));
                    *(float2*)(outH + node * HH + col) = r;
                } else if (PASS == 3) {
                    float2 tu = *(const float2*)(outH + node * HH + col);
                    float2 cf = *(const float2*)(outC + node * HH + col);
                    float2 r = make_float2(sigm(v0 + bb[col]) * tu.x + cf.x,
                                           sigm(v1 + bb[col + 1]) * tu.y + cf.y);
                    *(float2*)(outC + node * HH + col) = r;
                } else {
                    float2 cn = *(const float2*)(outC + node * HH + col);
                    float2 r = make_float2(
                        sigm(v0 + bb[128 + col]) * tanhf(cn.x),
                        sigm(v1 + bb[128 + col + 1]) * tanhf(cn.y));
                    *(float2*)(outH + node * HH + col) = r;
                }
            }
        }
    }
}

template <int PASS, int ATYPE, int NK>
__device__ __forceinline__ void run_pass(char* smem,
                                         const float* __restrict__ W, int ldw, int nb,
                                         const float* __restrict__ h,
                                         const float* __restrict__ x,
                                         const float* __restrict__ c,
                                         const int* sCh, const int* sLf,
                                         const float* sbUf, const float* sbI,
                                         const float* sbW,
                                         float* outH, float* outC, int base,
                                         int tid, int wm, int wn, int g, int t) {
    float acc[4][4][4];
#pragma unroll
    for (int a1 = 0; a1 < 4; a1++)
#pragma unroll
        for (int a2 = 0; a2 < 4; a2++)
#pragma unroll
            for (int a3 = 0; a3 < 4; a3++) acc[a1][a2][a3] = 0.f;

    loadA<ATYPE>(smem + A0_OFF, 0, h, x, sCh, sLf, base, tid);
    loadB(W, ldw, nb, smem + B0_OFF, 0, tid);
    CP_COMMIT();
#pragma unroll 1
    for (int kc = 0; kc < NK; kc++) {
        CP_WAIT0();
        __syncthreads();   // chunk kc visible to all; all warps past chunk kc-1
        if (kc + 1 < NK) {
            loadA<ATYPE>(smem + A0_OFF + ((kc + 1) & 1) * SLOT, kc + 1,
                         h, x, sCh, sLf, base, tid);
            loadB(W, ldw, nb, smem + B0_OFF + ((kc + 1) & 1) * SLOT, kc + 1, tid);
            CP_COMMIT();   // load of kc+1 overlaps compute of kc
        }
        compute_chunk((const float*)(smem + A0_OFF + (kc & 1) * SLOT),
                      (const float*)(smem + B0_OFF + (kc & 1) * SLOT),
                      acc, wm, wn, g, t);
    }
    epilogue<PASS>(acc, c, sCh, sLf, sbUf, sbI, sbW, outH, outC,
                   base, wm, wn, g, t);
}

__global__ void __launch_bounds__(256, 2)
tree_kernel(const float* __restrict__ x, const float* __restrict__ h,
            const float* __restrict__ c, const int* __restrict__ children,
            const int* __restrict__ is_leaf,
            const float* __restrict__ bWiou, const float* __restrict__ bUiou,
            const float* __restrict__ bUf,
            float* __restrict__ out, int N) {
    extern __shared__ char smem[];
    int*   sCh  = (int*)(smem + META_OFF);          // 256 i32
    int*   sLf  = (int*)(smem + META_OFF + 1024);   // 128 i32
    float* sbUf = (float*)(smem + META_OFF + 1536); // 256 f
    float* sbI  = (float*)(smem + META_OFF + 2560); // 384 f
    float* sbW  = (float*)(smem + META_OFF + 4096); // 384 f

    const int tid = threadIdx.x;
    const int wid = tid >> 5, lane = tid & 31;
    const int g = lane >> 2, t = lane & 3;
    const int wm = wid >> 2, wn = wid & 3;
    const int base = blockIdx.x * 128;

    sCh[tid] = children[base * 2 + tid];
    sbUf[tid] = bUf[tid];
    sbI[tid] = bUiou[tid];
    sbW[tid] = bWiou[tid];
    if (tid < 128) {
        sLf[tid] = is_leaf[base + tid];
        sbI[256 + tid] = bUiou[256 + tid];
        sbW[256 + tid] = bWiou[256 + tid];
    }
    __syncthreads();

    float* outH = out;
    float* outC = out + (size_t)N * HH;

    run_pass<0, 0, 8>(smem, g_Wf, 256, 0, h, x, c, sCh, sLf, sbUf, sbI, sbW,
                      outH, outC, base, tid, wm, wn, g, t);
    run_pass<1, 0, 8>(smem, g_Wf, 256, 128, h, x, c, sCh, sLf, sbUf, sbI, sbW,
                      outH, outC, base, tid, wm, wn, g, t);
    run_pass<2, 1, 12>(smem, g_Wiou, 384, 256, h, x, c, sCh, sLf, sbUf, sbI, sbW,
                       outH, outC, base, tid, wm, wn, g, t);
    run_pass<3, 1, 12>(smem, g_Wiou, 384, 0, h, x, c, sCh, sLf, sbUf, sbI, sbW,
                       outH, outC, base, tid, wm, wn, g, t);
    run_pass<4, 1, 12>(smem, g_Wiou, 384, 128, h, x, c, sCh, sLf, sbUf, sbI, sbW,
                       outH, outC, base, tid, wm, wn, g, t);
}

extern "C" void kernel_launch(void* const* d_in, const int* in_sizes, int n_in,
                              void* d_out, int out_size) {
    const float* x        = (const float*)d_in[0];
    const float* h        = (const float*)d_in[1];
    const float* c        = (const float*)d_in[2];
    const int*   children = (const int*)d_in[3];
    const int*   is_leaf  = (const int*)d_in[4];
    const float* W_iou    = (const float*)d_in[5];
    const float* b_Wiou   = (const float*)d_in[6];
    const float* U_iou    = (const float*)d_in[7];
    const float* b_Uiou   = (const float*)d_in[8];
    const float* U_f      = (const float*)d_in[9];
    const float* b_Uf     = (const float*)d_in[10];

    int N = in_sizes[1] / HH;   // 400000, multiple of 128

    cudaFuncSetAttribute(tree_kernel,
                         cudaFuncAttributeMaxDynamicSharedMemorySize, SMEM_BYTES);

    prep_kernel<<<(256 * 256 + 384 * 384 + 255) / 256, 256>>>(U_f, U_iou, W_iou);
    tree_kernel<<<N / 128, 256, SMEM_BYTES>>>(x, h, c, children, is_leaf,
                                              b_Wiou, b_Uiou, b_Uf,
                                              (float*)d_out, N);
}